// round 3
// baseline (speedup 1.0000x reference)
#include <cuda_runtime.h>

#define NF   128
#define NSEG 4096
#define MAXN 100000
#define MAXE 1000000

// ---- scratch (device globals: no runtime allocation allowed) ----
__device__ float    g_Pj[MAXN * NF];
__device__ float    g_Pi[MAXN * NF];
__device__ float    g_alpha[MAXE];
__device__ unsigned g_segmax[NSEG];
__device__ float    g_segsum[NSEG];

// monotone float<->uint encoding so atomicMax works on signed floats
__device__ __forceinline__ unsigned fenc(float f) {
    unsigned b = __float_as_uint(f);
    return (b & 0x80000000u) ? ~b : (b | 0x80000000u);
}
__device__ __forceinline__ float fdec(unsigned u) {
    return __uint_as_float((u & 0x80000000u) ? (u & 0x7FFFFFFFu) : ~u);
}

__global__ void init_kernel() {
    int i = blockIdx.x * blockDim.x + threadIdx.x;
    if (i < NSEG) { g_segmax[i] = 0u; g_segsum[i] = 0.0f; }
}

// ---------------------------------------------------------------------------
// Projection GEMM: P[n, c] = sum_k X[n, k] * W[k, c],  K = N = 128.
// Block: 256 threads -> 128 rows x 128 cols tile; thread tile 8 rows x 8 cols.
// X tile staged transposed (pad 129 -> conflict-free broadcast reads);
// W tile staged row-major; each thread reads cols {tx*4..+3, 64+tx*4..+3}
// (stride-4 float4 -> conflict-free).  ~1 B LDS per FMA -> FFMA-bound.
// ---------------------------------------------------------------------------
__global__ __launch_bounds__(256)
void proj_kernel(const float* __restrict__ X, const float* __restrict__ W,
                 int nrows, int which) {
    float* __restrict__ P = which ? g_Pi : g_Pj;
    __shared__ float xsT[32 * 129];   // [k][row], padded
    __shared__ float ws [32 * NF];    // [k][c]

    const int tid = threadIdx.x;
    const int tx  = tid & 15;         // col group: cols tx*4 and 64+tx*4
    const int ty  = tid >> 4;         // row group: rows ty*8 .. ty*8+7
    const int rowBase = blockIdx.x * 128;

    float acc[8][8];
#pragma unroll
    for (int i = 0; i < 8; i++)
#pragma unroll
        for (int j = 0; j < 8; j++) acc[i][j] = 0.0f;

    for (int kk = 0; kk < NF; kk += 32) {
        // stage X[rowBase..+127, kk..+31] transposed
#pragma unroll
        for (int p = 0; p < 4; p++) {
            int idx = p * 256 + tid;
            int row = idx >> 3;
            int kq  = idx & 7;
            int gr  = rowBase + row;
            float4 v = make_float4(0.f, 0.f, 0.f, 0.f);
            if (gr < nrows)
                v = *reinterpret_cast<const float4*>(X + gr * NF + kk + kq * 4);
            xsT[(kq * 4 + 0) * 129 + row] = v.x;
            xsT[(kq * 4 + 1) * 129 + row] = v.y;
            xsT[(kq * 4 + 2) * 129 + row] = v.z;
            xsT[(kq * 4 + 3) * 129 + row] = v.w;
        }
        // stage W[kk..+31, 0..127]
#pragma unroll
        for (int p = 0; p < 4; p++) {
            int idx = p * 256 + tid;
            int k  = idx >> 5;
            int cq = idx & 31;
            *reinterpret_cast<float4*>(ws + k * NF + cq * 4) =
                *reinterpret_cast<const float4*>(W + (kk + k) * NF + cq * 4);
        }
        __syncthreads();

#pragma unroll
        for (int k = 0; k < 32; k++) {
            float xv[8];
#pragma unroll
            for (int i = 0; i < 8; i++) xv[i] = xsT[k * 129 + ty * 8 + i];
            float4 w0 = *reinterpret_cast<const float4*>(ws + k * NF + tx * 4);
            float4 w1 = *reinterpret_cast<const float4*>(ws + k * NF + 64 + tx * 4);
#pragma unroll
            for (int i = 0; i < 8; i++) {
                acc[i][0] += xv[i] * w0.x;
                acc[i][1] += xv[i] * w0.y;
                acc[i][2] += xv[i] * w0.z;
                acc[i][3] += xv[i] * w0.w;
                acc[i][4] += xv[i] * w1.x;
                acc[i][5] += xv[i] * w1.y;
                acc[i][6] += xv[i] * w1.z;
                acc[i][7] += xv[i] * w1.w;
            }
        }
        __syncthreads();
    }

#pragma unroll
    for (int i = 0; i < 8; i++) {
        int gr = rowBase + ty * 8 + i;
        if (gr < nrows) {
            *reinterpret_cast<float4*>(P + gr * NF + tx * 4) =
                make_float4(acc[i][0], acc[i][1], acc[i][2], acc[i][3]);
            *reinterpret_cast<float4*>(P + gr * NF + 64 + tx * 4) =
                make_float4(acc[i][4], acc[i][5], acc[i][6], acc[i][7]);
        }
    }
}

// ---------------------------------------------------------------------------
// Per-edge: alpha[e] = PReLU(Pj[src] + Pi[dst] + bias) . mlpW + mlpb
// One warp per edge; lane handles 4 features (float4); shuffle reduction.
// P matrices (102 MB) are mostly L2-resident -> L2-BW bound.
// ---------------------------------------------------------------------------
__global__ __launch_bounds__(256)
void edge_alpha_kernel(const int* __restrict__ ei,
                       const float* __restrict__ bias,
                       const float* __restrict__ prelu_w,
                       const float* __restrict__ mlpW,
                       const float* __restrict__ mlpb, int E) {
    int gtid = blockIdx.x * blockDim.x + threadIdx.x;
    int e    = gtid >> 5;
    int lane = threadIdx.x & 31;
    if (e >= E) return;

    int src = ei[e];
    int dst = ei[E + e];

    float4 a  = *reinterpret_cast<const float4*>(g_Pj + src * NF + lane * 4);
    float4 b  = *reinterpret_cast<const float4*>(g_Pi + dst * NF + lane * 4);
    float4 bi = *reinterpret_cast<const float4*>(bias + lane * 4);
    float4 w  = *reinterpret_cast<const float4*>(mlpW + lane * 4);
    float  pw = prelu_w[0];

    float h0 = a.x + b.x + bi.x; h0 = (h0 >= 0.f) ? h0 : pw * h0;
    float h1 = a.y + b.y + bi.y; h1 = (h1 >= 0.f) ? h1 : pw * h1;
    float h2 = a.z + b.z + bi.z; h2 = (h2 >= 0.f) ? h2 : pw * h2;
    float h3 = a.w + b.w + bi.w; h3 = (h3 >= 0.f) ? h3 : pw * h3;

    float s = h0 * w.x + h1 * w.y + h2 * w.z + h3 * w.w;
#pragma unroll
    for (int o = 16; o > 0; o >>= 1)
        s += __shfl_xor_sync(0xffffffffu, s, o);

    if (lane == 0) g_alpha[e] = s + mlpb[0];
}

// ---------------------------------------------------------------------------
// Segmented max over sorted segment ids: warp-segmented suffix-max, one
// atomicMax per per-warp run head (~40K atomics total).
// ---------------------------------------------------------------------------
__global__ __launch_bounds__(256)
void segmax_kernel(const int* __restrict__ seg, int E) {
    int i    = blockIdx.x * blockDim.x + threadIdx.x;
    int lane = threadIdx.x & 31;
    float a = -3.4e38f;
    int   s = -1;
    if (i < E) { a = g_alpha[i]; s = seg[i]; }
#pragma unroll
    for (int o = 1; o < 32; o <<= 1) {
        float av = __shfl_down_sync(0xffffffffu, a, o);
        int   sv = __shfl_down_sync(0xffffffffu, s, o);
        if (lane + o < 32 && sv == s) a = fmaxf(a, av);
    }
    int sp = __shfl_up_sync(0xffffffffu, s, 1);
    bool head = (lane == 0) || (sp != s);
    if (i < E && head) atomicMax(&g_segmax[s], fenc(a));
}

// e = exp(alpha - segmax); store to out; warp-segmented suffix-sum + atomicAdd
__global__ __launch_bounds__(256)
void expsum_kernel(const int* __restrict__ seg, float* __restrict__ out, int E) {
    int i    = blockIdx.x * blockDim.x + threadIdx.x;
    int lane = threadIdx.x & 31;
    float e = 0.0f;
    int   s = -1;
    if (i < E) {
        s = seg[i];
        float m = fdec(g_segmax[s]);
        e = __expf(g_alpha[i] - m);
        out[i] = e;
    }
    float sum = e;
#pragma unroll
    for (int o = 1; o < 32; o <<= 1) {
        float av = __shfl_down_sync(0xffffffffu, sum, o);
        int   sv = __shfl_down_sync(0xffffffffu, s, o);
        if (lane + o < 32 && sv == s) sum += av;
    }
    int sp = __shfl_up_sync(0xffffffffu, s, 1);
    bool head = (lane == 0) || (sp != s);
    if (i < E && head) atomicAdd(&g_segsum[s], sum);
}

__global__ __launch_bounds__(256)
void norm_kernel(const int* __restrict__ seg, float* __restrict__ out, int E) {
    int i = blockIdx.x * blockDim.x + threadIdx.x;
    if (i < E) out[i] = out[i] / (g_segsum[seg[i]] + 1e-16f);
}

// ---------------------------------------------------------------------------
extern "C" void kernel_launch(void* const* d_in, const int* in_sizes, int n_in,
                              void* d_out, int out_size) {
    const float* x_j   = (const float*)d_in[0];
    const float* x_i   = (const float*)d_in[1];
    const int*   ei    = (const int*)  d_in[2];
    const int*   seg   = (const int*)  d_in[3];
    const float* w_j   = (const float*)d_in[4];
    const float* w_i   = (const float*)d_in[5];
    const float* bias  = (const float*)d_in[6];
    const float* prelu = (const float*)d_in[7];
    const float* mlpW  = (const float*)d_in[8];
    const float* mlpb  = (const float*)d_in[9];

    int nnodes = in_sizes[0] / NF;
    int E      = in_sizes[3];
    float* out = (float*)d_out;

    init_kernel<<<(NSEG + 255) / 256, 256>>>();

    int gblocks = (nnodes + 127) / 128;
    proj_kernel<<<gblocks, 256>>>(x_j, w_j, nnodes, 0);
    proj_kernel<<<gblocks, 256>>>(x_i, w_i, nnodes, 1);

    long long nthreads = (long long)E * 32;
    edge_alpha_kernel<<<(unsigned)((nthreads + 255) / 256), 256>>>(
        ei, bias, prelu, mlpW, mlpb, E);

    int eb = (E + 255) / 256;
    segmax_kernel<<<eb, 256>>>(seg, E);
    expsum_kernel<<<eb, 256>>>(seg, out, E);
    norm_kernel  <<<eb, 256>>>(seg, out, E);
}